// round 15
// baseline (speedup 1.0000x reference)
#include <cuda_runtime.h>
#include <cuda_fp16.h>
#include <cstdint>

// ---------------------------------------------------------------------------
// MultiheadAttention: b=2, n=2048, c=1024, h=16, d=64
// Round 15: GEMM warp tile 64x64 (128-thread CTAs, 33% less LDS per MMA,
//   32-MMA issue runs); attention 3-stage KV pipeline (prefetch distance 2).
// ---------------------------------------------------------------------------

namespace {
constexpr int B_ = 2;
constexpr int N_ = 2048;
constexpr int C_ = 1024;
constexpr int H_ = 16;
constexpr int D_ = 64;
constexpr float QSCALE = 0.125f * 1.44269504088896340736f;  // scale * log2(e)

constexpr int XSEG = 4096 * 1024;
constexpr int WSEG = 1024 * 1024;

// GEMM tiling: CTA tile 128(M) x 128(N), 128 threads (4 warps, 2Mx2N),
// warp tile 64x64. K-super 64, ring of 2 buffers, 2 CTAs/SM.
constexpr int BM = 128, BN = 128;
constexpr int GPITCH = 144;                    // 128 B data + 16 pad
constexpr int TILE_A = BM * GPITCH;            // 18432 B
constexpr int TILE_B = BN * GPITCH;            // 18432 B
constexpr int SUPER_PS = TILE_A + TILE_B;      // 36864 B
constexpr int GEMM_SMEM = 2 * SUPER_PS;        // 73728 B -> 2 CTAs/SM
constexpr int NSUPER = C_ / 64;                // 16

// Attention tiling: Q hi/lo resident; K,V single fp16, 3-stage ring.
constexpr int APITCH = 144;
constexpr int QTILE = 128 * APITCH;            // 18432 B per Q half
constexpr int KTILE = 64 * APITCH;             // 9216 B
constexpr int KV_STAGE = 2 * KTILE;            // 18432 B
constexpr int ATTN_SMEM = 2 * QTILE + 3 * KV_STAGE;  // 92160 B -> 2 CTAs/SM
}

// fp16 buffers
__device__ __half g_X1[3 * XSEG];
__device__ __half g_W[4 * WSEG];
// Head-layout projections
__device__ __half g_Qhi[B_ * H_ * N_ * D_];
__device__ __half g_Qlo[B_ * H_ * N_ * D_];
__device__ __half g_K1[B_ * H_ * N_ * D_];
__device__ __half g_V1[B_ * H_ * N_ * D_];
// Attention output single fp16
__device__ __half g_AO1[XSEG];

// ---------------------------------------------------------------------------
__device__ __forceinline__ uint32_t smem_u32(const void* p) {
    uint32_t a;
    asm("{ .reg .u64 t; cvta.to.shared.u64 t, %1; cvt.u32.u64 %0, t; }" : "=r"(a) : "l"(p));
    return a;
}
__device__ __forceinline__ void ldm_x4(uint32_t* r, uint32_t addr) {
    asm volatile("ldmatrix.sync.aligned.m8n8.x4.shared.b16 {%0,%1,%2,%3}, [%4];"
                 : "=r"(r[0]), "=r"(r[1]), "=r"(r[2]), "=r"(r[3]) : "r"(addr));
}
__device__ __forceinline__ void ldm_x4_t(uint32_t* r, uint32_t addr) {
    asm volatile("ldmatrix.sync.aligned.m8n8.x4.trans.shared.b16 {%0,%1,%2,%3}, [%4];"
                 : "=r"(r[0]), "=r"(r[1]), "=r"(r[2]), "=r"(r[3]) : "r"(addr));
}
__device__ __forceinline__ void mma16816(float* c, const uint32_t* a, const uint32_t* b) {
    asm volatile(
        "mma.sync.aligned.m16n8k16.row.col.f32.f16.f16.f32 "
        "{%0,%1,%2,%3}, {%4,%5,%6,%7}, {%8,%9}, {%0,%1,%2,%3};"
        : "+f"(c[0]), "+f"(c[1]), "+f"(c[2]), "+f"(c[3])
        : "r"(a[0]), "r"(a[1]), "r"(a[2]), "r"(a[3]), "r"(b[0]), "r"(b[1]));
}
__device__ __forceinline__ uint32_t pack_h2(float a, float b) {
    __half2 h = __floats2half2_rn(a, b);
    return *reinterpret_cast<uint32_t*>(&h);
}
__device__ __forceinline__ void split2h(float a, float b, uint32_t& hi, uint32_t& lo) {
    __half2 h = __floats2half2_rn(a, b);
    float2 f = __half22float2(h);
    __half2 l = __floats2half2_rn(a - f.x, b - f.y);
    hi = *reinterpret_cast<uint32_t*>(&h);
    lo = *reinterpret_cast<uint32_t*>(&l);
}
__device__ __forceinline__ float ex2f(float x) {
    float y;
    asm("ex2.approx.ftz.f32 %0, %1;" : "=f"(y) : "f"(x));
    return y;
}
__device__ __forceinline__ void cpa16(uint32_t dst, const void* src) {
    asm volatile("cp.async.cg.shared.global [%0], [%1], 16;" :: "r"(dst), "l"(src));
}
__device__ __forceinline__ void cp_commit() {
    asm volatile("cp.async.commit_group;" ::: "memory");
}
template <int n> __device__ __forceinline__ void cp_wait() {
    asm volatile("cp.async.wait_group %0;" :: "n"(n) : "memory");
}

// ---------------------------------------------------------------------------
// K0: fp32 -> fp16 single converter
// ---------------------------------------------------------------------------
__global__ __launch_bounds__(256)
void split_convert_kernel(const float* __restrict__ q, const float* __restrict__ k,
                          const float* __restrict__ v,
                          const float* __restrict__ wq, const float* __restrict__ wk,
                          const float* __restrict__ wv, const float* __restrict__ wo)
{
    const int seg = blockIdx.y;
    const int idx = blockIdx.x * 256 + threadIdx.x;

    const float* src;
    __half* dst;
    int n4;
    switch (seg) {
        case 0: src = q;  dst = g_X1;            n4 = XSEG / 4; break;
        case 1: src = k;  dst = g_X1 + XSEG;     n4 = XSEG / 4; break;
        case 2: src = v;  dst = g_X1 + 2 * XSEG; n4 = XSEG / 4; break;
        case 3: src = wq; dst = g_W;             n4 = WSEG / 4; break;
        case 4: src = wk; dst = g_W + WSEG;      n4 = WSEG / 4; break;
        case 5: src = wv; dst = g_W + 2 * WSEG;  n4 = WSEG / 4; break;
        default: src = wo; dst = g_W + 3 * WSEG; n4 = WSEG / 4; break;
    }
    if (idx >= n4) return;
    float4 x = reinterpret_cast<const float4*>(src)[idx];
    reinterpret_cast<uint2*>(dst)[idx] =
        make_uint2(pack_h2(x.x, x.y), pack_h2(x.z, x.w));
}

// ---------------------------------------------------------------------------
// GEMM tile: Y = A @ W^T + bias, single fp16 operands.
// 128 threads, 4 warps (2Mx2N), warp tile 64x64, K-super 64.
// outMode: 0 = head-layout split (Q), 1 = head-layout single (K/V),
//          2 = flat fp32 (out-proj)
// ---------------------------------------------------------------------------
__device__ __forceinline__ void gemm_h1_tile(
    const __half* __restrict__ As, const __half* __restrict__ Bs,
    const float* __restrict__ bias,
    float* __restrict__ Yf32, __half* __restrict__ Yhi, __half* __restrict__ Ylo,
    float oscale, int outMode, int rowBase, int colBase, char* sm)
{
    const int tid = threadIdx.x;
    const int lane = tid & 31;
    const int wid = tid >> 5;
    const int warp_m = wid & 1;        // 2 x 64 rows
    const int warp_n = wid >> 1;       // 2 x 64 cols
    const uint32_t sb = smem_u32(sm);

    float acc[4][8][4] = {};           // [am 16-row][nf 8-col][frag]

    const uint32_t aRow = (uint32_t)(warp_m * 64 + (lane & 15)) * GPITCH + (uint32_t)(lane & 16);
    const uint32_t bRow = (uint32_t)(warp_n * 64 + ((lane & 7) | ((lane & 16) >> 1))) * GPITCH
                          + (uint32_t)((lane & 8) * 2);

    auto load_super = [&](int k0, int buf) {
        const uint32_t base = sb + (uint32_t)buf * SUPER_PS;
        #pragma unroll
        for (int l = 0; l < 8; ++l) {
            const int id = tid + l * 128;            // 0..1023: 128 rows x 8 chunks
            const int r = id >> 3, c = id & 7;
            const uint32_t off = (uint32_t)(r * GPITCH + c * 16);
            cpa16(base + off,          As + (size_t)(rowBase + r) * C_ + k0 + c * 8);
            cpa16(base + TILE_A + off, Bs + (size_t)(colBase + r) * C_ + k0 + c * 8);
        }
    };

    load_super(0, 0);
    cp_commit();

    for (int s = 0; s < NSUPER; ++s) {
        cp_wait<0>();
        __syncthreads();
        if (s + 1 < NSUPER) load_super((s + 1) * 64, (s + 1) & 1);
        cp_commit();

        const uint32_t stB = sb + (uint32_t)(s & 1) * SUPER_PS;
        const uint32_t sB = stB + TILE_A;
        #pragma unroll
        for (int ks = 0; ks < 4; ++ks) {
            uint32_t a4[4][4];
            #pragma unroll
            for (int am = 0; am < 4; ++am)
                ldm_x4(a4[am], stB + aRow + am * 16 * GPITCH + ks * 32);
            #pragma unroll
            for (int t = 0; t < 4; ++t) {
                uint32_t b4[4];
                ldm_x4(b4, sB + bRow + t * 16 * GPITCH + ks * 32);
                #pragma unroll
                for (int am = 0; am < 4; ++am)
                    #pragma unroll
                    for (int sub = 0; sub < 2; ++sub)
                        mma16816(acc[am][t * 2 + sub], a4[am], &b4[2 * sub]);
            }
        }
    }

    const int r = lane >> 2;
    const int cc = (lane & 3) * 2;
    #pragma unroll
    for (int am = 0; am < 4; ++am) {
        #pragma unroll
        for (int nf = 0; nf < 8; ++nf) {
            const float* c = acc[am][nf];
            const int col0 = colBase + warp_n * 64 + nf * 8 + cc;
            const int row0 = rowBase + warp_m * 64 + am * 16 + r;
            const float b0 = bias[col0], b1 = bias[col0 + 1];
            #pragma unroll
            for (int rr = 0; rr < 2; ++rr) {
                const int row = row0 + rr * 8;
                const float v0 = (c[rr * 2 + 0] + b0) * oscale;
                const float v1 = (c[rr * 2 + 1] + b1) * oscale;
                if (outMode == 2) {
                    float* p = &Yf32[(size_t)row * C_ + col0];
                    p[0] = v0; p[1] = v1;
                } else {
                    const int bb = row >> 11, i = row & (N_ - 1);
                    const int h = col0 >> 6, dd = col0 & 63;
                    const size_t idx = ((size_t)(bb * H_ + h) * N_ + i) * D_ + dd;
                    if (outMode == 0) {
                        uint32_t hi, lo;
                        split2h(v0, v1, hi, lo);
                        *reinterpret_cast<uint32_t*>(&Yhi[idx]) = hi;
                        *reinterpret_cast<uint32_t*>(&Ylo[idx]) = lo;
                    } else {
                        *reinterpret_cast<uint32_t*>(&Yhi[idx]) = pack_h2(v0, v1);
                    }
                }
            }
        }
    }
}

__global__ __launch_bounds__(128, 2)
void mha_qkv_ps_kernel(const float* __restrict__ bq, const float* __restrict__ bk,
                       const float* __restrict__ bv)
{
    extern __shared__ __align__(16) char sm[];
    const int z = blockIdx.z;
    const __half* As = g_X1 + (size_t)z * XSEG;
    const __half* Bs = g_W + (size_t)z * WSEG;
    if (z == 0) {
        gemm_h1_tile(As, Bs, bq, nullptr, g_Qhi, g_Qlo, QSCALE, 0,
                     blockIdx.y * BM, blockIdx.x * BN, sm);
    } else if (z == 1) {
        gemm_h1_tile(As, Bs, bk, nullptr, g_K1, nullptr, 1.0f, 1,
                     blockIdx.y * BM, blockIdx.x * BN, sm);
    } else {
        gemm_h1_tile(As, Bs, bv, nullptr, g_V1, nullptr, 1.0f, 1,
                     blockIdx.y * BM, blockIdx.x * BN, sm);
    }
}

__global__ __launch_bounds__(128, 2)
void mha_out_ps_kernel(const float* __restrict__ bo, float* __restrict__ out)
{
    extern __shared__ __align__(16) char sm[];
    gemm_h1_tile(g_AO1, g_W + 3 * WSEG, bo, out, nullptr, nullptr,
                 1.0f, 2, blockIdx.y * BM, blockIdx.x * BN, sm);
}

// ---------------------------------------------------------------------------
// K2: fp16 tensor-core flash attention. Q split (A), K/V single; P hi-only.
// 3-stage KV ring, prefetch distance 2.
// ---------------------------------------------------------------------------
__device__ __forceinline__ void issue_kv(uint32_t dstbase, int tid,
                                         const __half* kk, const __half* vv)
{
    #pragma unroll
    for (int l = 0; l < 2; l++) {
        int cid = tid + l * 256;
        int row = cid >> 3, c8 = cid & 7;
        uint32_t off = (uint32_t)(row * APITCH + c8 * 16);
        const size_t g = (size_t)row * 64 + c8 * 8;
        cpa16(dstbase + off,         kk + g);
        cpa16(dstbase + KTILE + off, vv + g);
    }
}

__global__ __launch_bounds__(256, 2)
void mha_attn_tc_kernel()
{
    extern __shared__ __align__(16) char sm[];
    const uint32_t sb = smem_u32(sm);
    const int tid = threadIdx.x;
    const int lane = tid & 31;
    const int wid = tid >> 5;
    const int bh = blockIdx.y;
    const int qt = blockIdx.x;

    const size_t hbase = (size_t)bh * N_ * D_;
    {
        const __half* qh = g_Qhi + hbase + (size_t)qt * 128 * D_;
        const __half* ql = g_Qlo + hbase + (size_t)qt * 128 * D_;
        #pragma unroll
        for (int l = 0; l < 4; l++) {
            int cid = tid + l * 256;
            int row = cid >> 3, c8 = cid & 7;
            const size_t g = (size_t)row * 64 + c8 * 8;
            uint32_t off = (uint32_t)(row * APITCH + c8 * 16);
            *reinterpret_cast<uint4*>(sm + off) = *reinterpret_cast<const uint4*>(qh + g);
            *reinterpret_cast<uint4*>(sm + QTILE + off) = *reinterpret_cast<const uint4*>(ql + g);
        }
    }

    const uint32_t kvb = sb + 2 * QTILE;
    issue_kv(kvb, tid, g_K1 + hbase, g_V1 + hbase);
    cp_commit();
    issue_kv(kvb + KV_STAGE, tid, g_K1 + hbase + 64 * D_, g_V1 + hbase + 64 * D_);
    cp_commit();

    float mA = -1e30f, mB = -1e30f, lA = 0.0f, lB = 0.0f;
    float oacc[8][4] = {};

    const uint32_t qrow = sb + (uint32_t)((wid * 16 + (lane & 15)) * APITCH + (lane >> 4) * 16);
    const uint32_t krow = (uint32_t)((((lane & 7) | ((lane & 16) >> 1)) * APITCH) + (lane & 8) * 2);
    const uint32_t vrow = (uint32_t)((lane & 15) * APITCH + (lane >> 4) * 16);

    constexpr int NKT = N_ / 64;   // 32
    int s_cur = 0, s_ld = 2;
    for (int kt = 0; kt < NKT; ++kt) {
        cp_wait<1>();        // stage for kt resident
        __syncthreads();     // all warps finished kt-1 -> its stage reusable
        if (kt + 2 < NKT) {
            issue_kv(kvb + (uint32_t)s_ld * KV_STAGE, tid,
                     g_K1 + hbase + (size_t)(kt + 2) * 64 * D_,
                     g_V1 + hbase + (size_t)(kt + 2) * 64 * D_);
        }
        cp_commit();

        const uint32_t kb = kvb + (uint32_t)s_cur * KV_STAGE;
        const uint32_t Ks = kb, Vs = kb + KTILE;

        // S (16 q-rows x 64 keys), log2 domain
        float sacc[8][4] = {};
        #pragma unroll
        for (int ks = 0; ks < 4; ++ks) {
            uint32_t qh4[4], ql4[4];
            ldm_x4(qh4, qrow + ks * 32);
            ldm_x4(ql4, qrow + QTILE + ks * 32);
            #pragma unroll
            for (int t = 0; t < 4; ++t) {
                uint32_t k4[4];
                ldm_x4(k4, Ks + krow + t * 16 * APITCH + ks * 32);
                mma16816(sacc[t * 2 + 0], qh4, &k4[0]);
                mma16816(sacc[t * 2 + 1], qh4, &k4[2]);
                mma16816(sacc[t * 2 + 0], ql4, &k4[0]);
                mma16816(sacc[t * 2 + 1], ql4, &k4[2]);
            }
        }

        // Online softmax (base-2)
        float tA = -1e30f, tB = -1e30f;
        #pragma unroll
        for (int f = 0; f < 8; ++f) {
            tA = fmaxf(tA, fmaxf(sacc[f][0], sacc[f][1]));
            tB = fmaxf(tB, fmaxf(sacc[f][2], sacc[f][3]));
        }
        tA = fmaxf(tA, __shfl_xor_sync(0xffffffffu, tA, 1));
        tA = fmaxf(tA, __shfl_xor_sync(0xffffffffu, tA, 2));
        tB = fmaxf(tB, __shfl_xor_sync(0xffffffffu, tB, 1));
        tB = fmaxf(tB, __shfl_xor_sync(0xffffffffu, tB, 2));
        const float nmA = fmaxf(mA, tA), nmB = fmaxf(mB, tB);
        const float cA = ex2f(mA - nmA), cB = ex2f(mB - nmB);
        mA = nmA; mB = nmB;

        float psA = 0.0f, psB = 0.0f;
        #pragma unroll
        for (int f = 0; f < 8; ++f) {
            float p0 = ex2f(sacc[f][0] - mA);
            float p1 = ex2f(sacc[f][1] - mA);
            float p2 = ex2f(sacc[f][2] - mB);
            float p3 = ex2f(sacc[f][3] - mB);
            sacc[f][0] = p0; sacc[f][1] = p1; sacc[f][2] = p2; sacc[f][3] = p3;
            psA += p0 + p1; psB += p2 + p3;
        }
        lA = lA * cA + psA;
        lB = lB * cB + psB;
        #pragma unroll
        for (int nf = 0; nf < 8; ++nf) {
            oacc[nf][0] *= cA; oacc[nf][1] *= cA;
            oacc[nf][2] *= cB; oacc[nf][3] *= cB;
        }

        // O += P @ V  (P hi-only fp16; V single)
        #pragma unroll
        for (int ks = 0; ks < 4; ++ks) {
            uint32_t phi[4];
            phi[0] = pack_h2(sacc[2 * ks][0],     sacc[2 * ks][1]);
            phi[1] = pack_h2(sacc[2 * ks][2],     sacc[2 * ks][3]);
            phi[2] = pack_h2(sacc[2 * ks + 1][0], sacc[2 * ks + 1][1]);
            phi[3] = pack_h2(sacc[2 * ks + 1][2], sacc[2 * ks + 1][3]);
            const uint32_t vb = vrow + (uint32_t)(16 * ks * APITCH);
            #pragma unroll
            for (int dg = 0; dg < 4; ++dg) {
                uint32_t v4[4];
                ldm_x4_t(v4, Vs + vb + dg * 32);
                mma16816(oacc[2 * dg],     phi, &v4[0]);
                mma16816(oacc[2 * dg + 1], phi, &v4[2]);
            }
        }

        s_cur = (s_cur == 2) ? 0 : s_cur + 1;
        s_ld  = (s_ld  == 2) ? 0 : s_ld  + 1;
    }

    lA += __shfl_xor_sync(0xffffffffu, lA, 1);
    lA += __shfl_xor_sync(0xffffffffu, lA, 2);
    lB += __shfl_xor_sync(0xffffffffu, lB, 1);
    lB += __shfl_xor_sync(0xffffffffu, lB, 2);
    const float iA = 1.0f / lA, iB = 1.0f / lB;

    const int b = bh >> 4;
    const int h = bh & 15;
    const int rowA = qt * 128 + wid * 16 + (lane >> 2);
    #pragma unroll
    for (int nf = 0; nf < 8; ++nf) {
        const int d0 = nf * 8 + (lane & 3) * 2;
        const size_t iA0 = (size_t)(b * N_ + rowA) * C_ + h * 64 + d0;
        const size_t iB0 = (size_t)(b * N_ + rowA + 8) * C_ + h * 64 + d0;
        *reinterpret_cast<uint32_t*>(&g_AO1[iA0]) = pack_h2(oacc[nf][0] * iA, oacc[nf][1] * iA);
        *reinterpret_cast<uint32_t*>(&g_AO1[iB0]) = pack_h2(oacc[nf][2] * iB, oacc[nf][3] * iB);
    }
}

// ---------------------------------------------------------------------------
extern "C" void kernel_launch(void* const* d_in, const int* in_sizes, int n_in,
                              void* d_out, int out_size)
{
    (void)in_sizes; (void)n_in; (void)out_size;
    const float* q  = (const float*)d_in[0];
    const float* k  = (const float*)d_in[1];
    const float* v  = (const float*)d_in[2];
    const float* wq = (const float*)d_in[3];
    const float* bq = (const float*)d_in[4];
    const float* wk = (const float*)d_in[5];
    const float* bk = (const float*)d_in[6];
    const float* wv = (const float*)d_in[7];
    const float* bv = (const float*)d_in[8];
    const float* wo = (const float*)d_in[9];
    const float* bo = (const float*)d_in[10];
    float* out = (float*)d_out;

    cudaFuncSetAttribute(mha_qkv_ps_kernel,
                         cudaFuncAttributeMaxDynamicSharedMemorySize, GEMM_SMEM);
    cudaFuncSetAttribute(mha_out_ps_kernel,
                         cudaFuncAttributeMaxDynamicSharedMemorySize, GEMM_SMEM);
    cudaFuncSetAttribute(mha_attn_tc_kernel,
                         cudaFuncAttributeMaxDynamicSharedMemorySize, ATTN_SMEM);

    dim3 gsplit(XSEG / 4 / 256, 7);
    split_convert_kernel<<<gsplit, 256>>>(q, k, v, wq, wk, wv, wo);

    dim3 gproj(C_ / BN, (B_ * N_) / BM, 3);   // 8 x 32 x 3
    mha_qkv_ps_kernel<<<gproj, 128, GEMM_SMEM>>>(bq, bk, bv);

    dim3 gattn(N_ / 128, B_ * H_);            // 16 x 32
    mha_attn_tc_kernel<<<gattn, 256, ATTN_SMEM>>>();

    dim3 gout(C_ / BN, (B_ * N_) / BM);       // 8 x 32
    mha_out_ps_kernel<<<gout, 128, GEMM_SMEM>>>(bo, out);
}

// round 16
// speedup vs baseline: 1.0178x; 1.0178x over previous
#include <cuda_runtime.h>
#include <cuda_fp16.h>
#include <cstdint>

// ---------------------------------------------------------------------------
// MultiheadAttention: b=2, n=2048, c=1024, h=16, d=64
// Round 16: R14 structure restored (256-thread GEMM CTAs, warp tile 32x64;
//   attention 2-stage KV) + GEMM 3-super ring with cp_wait<1> (prefetch=2).
// ---------------------------------------------------------------------------

namespace {
constexpr int B_ = 2;
constexpr int N_ = 2048;
constexpr int C_ = 1024;
constexpr int H_ = 16;
constexpr int D_ = 64;
constexpr float QSCALE = 0.125f * 1.44269504088896340736f;  // scale * log2(e)

constexpr int XSEG = 4096 * 1024;
constexpr int WSEG = 1024 * 1024;

// GEMM tiling: CTA tile 128(M) x 128(N), 256 threads (8 warps, 4Mx2N),
// warp tile 32x64. K-super 64, ring of 3 buffers, cp_wait<1>, 2 CTAs/SM.
constexpr int BM = 128, BN = 128;
constexpr int GPITCH = 144;                    // 128 B data + 16 pad
constexpr int TILE_A = BM * GPITCH;            // 18432 B
constexpr int TILE_B = BN * GPITCH;            // 18432 B
constexpr int SUPER_PS = TILE_A + TILE_B;      // 36864 B
constexpr int NRING = 3;
constexpr int GEMM_SMEM = NRING * SUPER_PS;    // 110592 B -> 2 CTAs/SM
constexpr int NSUPER = C_ / 64;                // 16

// Attention tiling: Q hi/lo resident; K,V single fp16, double-buffered.
constexpr int APITCH = 144;
constexpr int QTILE = 128 * APITCH;            // 18432 B per Q half
constexpr int KTILE = 64 * APITCH;             // 9216 B
constexpr int KV_STAGE = 2 * KTILE;            // 18432 B
constexpr int ATTN_SMEM = 2 * QTILE + 2 * KV_STAGE;  // 73728 B -> 2 CTAs/SM
}

// fp16 buffers
__device__ __half g_X1[3 * XSEG];
__device__ __half g_W[4 * WSEG];
// Head-layout projections
__device__ __half g_Qhi[B_ * H_ * N_ * D_];
__device__ __half g_Qlo[B_ * H_ * N_ * D_];
__device__ __half g_K1[B_ * H_ * N_ * D_];
__device__ __half g_V1[B_ * H_ * N_ * D_];
// Attention output single fp16
__device__ __half g_AO1[XSEG];

// ---------------------------------------------------------------------------
__device__ __forceinline__ uint32_t smem_u32(const void* p) {
    uint32_t a;
    asm("{ .reg .u64 t; cvta.to.shared.u64 t, %1; cvt.u32.u64 %0, t; }" : "=r"(a) : "l"(p));
    return a;
}
__device__ __forceinline__ void ldm_x4(uint32_t* r, uint32_t addr) {
    asm volatile("ldmatrix.sync.aligned.m8n8.x4.shared.b16 {%0,%1,%2,%3}, [%4];"
                 : "=r"(r[0]), "=r"(r[1]), "=r"(r[2]), "=r"(r[3]) : "r"(addr));
}
__device__ __forceinline__ void ldm_x4_t(uint32_t* r, uint32_t addr) {
    asm volatile("ldmatrix.sync.aligned.m8n8.x4.trans.shared.b16 {%0,%1,%2,%3}, [%4];"
                 : "=r"(r[0]), "=r"(r[1]), "=r"(r[2]), "=r"(r[3]) : "r"(addr));
}
__device__ __forceinline__ void mma16816(float* c, const uint32_t* a, const uint32_t* b) {
    asm volatile(
        "mma.sync.aligned.m16n8k16.row.col.f32.f16.f16.f32 "
        "{%0,%1,%2,%3}, {%4,%5,%6,%7}, {%8,%9}, {%0,%1,%2,%3};"
        : "+f"(c[0]), "+f"(c[1]), "+f"(c[2]), "+f"(c[3])
        : "r"(a[0]), "r"(a[1]), "r"(a[2]), "r"(a[3]), "r"(b[0]), "r"(b[1]));
}
__device__ __forceinline__ uint32_t pack_h2(float a, float b) {
    __half2 h = __floats2half2_rn(a, b);
    return *reinterpret_cast<uint32_t*>(&h);
}
__device__ __forceinline__ void split2h(float a, float b, uint32_t& hi, uint32_t& lo) {
    __half2 h = __floats2half2_rn(a, b);
    float2 f = __half22float2(h);
    __half2 l = __floats2half2_rn(a - f.x, b - f.y);
    hi = *reinterpret_cast<uint32_t*>(&h);
    lo = *reinterpret_cast<uint32_t*>(&l);
}
__device__ __forceinline__ float ex2f(float x) {
    float y;
    asm("ex2.approx.ftz.f32 %0, %1;" : "=f"(y) : "f"(x));
    return y;
}
__device__ __forceinline__ void cpa16(uint32_t dst, const void* src) {
    asm volatile("cp.async.cg.shared.global [%0], [%1], 16;" :: "r"(dst), "l"(src));
}
__device__ __forceinline__ void cp_commit() {
    asm volatile("cp.async.commit_group;" ::: "memory");
}
template <int n> __device__ __forceinline__ void cp_wait() {
    asm volatile("cp.async.wait_group %0;" :: "n"(n) : "memory");
}

// ---------------------------------------------------------------------------
// K0: fp32 -> fp16 single converter
// ---------------------------------------------------------------------------
__global__ __launch_bounds__(256)
void split_convert_kernel(const float* __restrict__ q, const float* __restrict__ k,
                          const float* __restrict__ v,
                          const float* __restrict__ wq, const float* __restrict__ wk,
                          const float* __restrict__ wv, const float* __restrict__ wo)
{
    const int seg = blockIdx.y;
    const int idx = blockIdx.x * 256 + threadIdx.x;

    const float* src;
    __half* dst;
    int n4;
    switch (seg) {
        case 0: src = q;  dst = g_X1;            n4 = XSEG / 4; break;
        case 1: src = k;  dst = g_X1 + XSEG;     n4 = XSEG / 4; break;
        case 2: src = v;  dst = g_X1 + 2 * XSEG; n4 = XSEG / 4; break;
        case 3: src = wq; dst = g_W;             n4 = WSEG / 4; break;
        case 4: src = wk; dst = g_W + WSEG;      n4 = WSEG / 4; break;
        case 5: src = wv; dst = g_W + 2 * WSEG;  n4 = WSEG / 4; break;
        default: src = wo; dst = g_W + 3 * WSEG; n4 = WSEG / 4; break;
    }
    if (idx >= n4) return;
    float4 x = reinterpret_cast<const float4*>(src)[idx];
    reinterpret_cast<uint2*>(dst)[idx] =
        make_uint2(pack_h2(x.x, x.y), pack_h2(x.z, x.w));
}

// ---------------------------------------------------------------------------
// GEMM tile: Y = A @ W^T + bias, single fp16 operands (1 MMA/product).
// 256 threads, 8 warps (4Mx2N), warp tile 32x64, K-super 64, 3-buffer ring.
// outMode: 0 = head-layout split (Q), 1 = head-layout single (K/V),
//          2 = flat fp32 (out-proj)
// ---------------------------------------------------------------------------
__device__ __forceinline__ void gemm_h1_tile(
    const __half* __restrict__ As, const __half* __restrict__ Bs,
    const float* __restrict__ bias,
    float* __restrict__ Yf32, __half* __restrict__ Yhi, __half* __restrict__ Ylo,
    float oscale, int outMode, int rowBase, int colBase, char* sm)
{
    const int tid = threadIdx.x;
    const int lane = tid & 31;
    const int wid = tid >> 5;
    const int warp_m = wid & 3;        // 4 x 32 rows
    const int warp_n = wid >> 2;       // 2 x 64 cols
    const uint32_t sb = smem_u32(sm);

    float acc[2][8][4] = {};

    const uint32_t aRow = (uint32_t)(warp_m * 32 + (lane & 15)) * GPITCH + (uint32_t)(lane & 16);
    const uint32_t bRow = (uint32_t)(warp_n * 64 + ((lane & 7) | ((lane & 16) >> 1))) * GPITCH
                          + (uint32_t)((lane & 8) * 2);

    auto load_super = [&](int k0, int buf) {
        const uint32_t base = sb + (uint32_t)buf * SUPER_PS;
        #pragma unroll
        for (int l = 0; l < 4; ++l) {
            const int id = tid + l * 256;            // 128 rows x 8 chunks
            const int r = id >> 3, c = id & 7;
            const uint32_t off = (uint32_t)(r * GPITCH + c * 16);
            cpa16(base + off,          As + (size_t)(rowBase + r) * C_ + k0 + c * 8);
            cpa16(base + TILE_A + off, Bs + (size_t)(colBase + r) * C_ + k0 + c * 8);
        }
    };

    // Prologue: supers 0,1 in flight
    load_super(0, 0);  cp_commit();
    load_super(64, 1); cp_commit();

    int s_cur = 0, s_ld = 2;
    for (int s = 0; s < NSUPER; ++s) {
        cp_wait<1>();        // super s resident; s+1 may still be in flight
        __syncthreads();     // all warps finished super s-1 -> its buffer free

        if (s + 2 < NSUPER) load_super((s + 2) * 64, s_ld);
        cp_commit();         // unconditional: one group per iteration

        const uint32_t stB = sb + (uint32_t)s_cur * SUPER_PS;
        const uint32_t sB = stB + TILE_A;
        #pragma unroll
        for (int ks = 0; ks < 4; ++ks) {
            uint32_t a4[2][4];
            ldm_x4(a4[0], stB + aRow + ks * 32);
            ldm_x4(a4[1], stB + aRow + 16 * GPITCH + ks * 32);
            #pragma unroll
            for (int t = 0; t < 4; ++t) {
                uint32_t b4[4];
                ldm_x4(b4, sB + bRow + t * 16 * GPITCH + ks * 32);
                #pragma unroll
                for (int f = 0; f < 2; ++f)
                    #pragma unroll
                    for (int sub = 0; sub < 2; ++sub)
                        mma16816(acc[f][t * 2 + sub], a4[f], &b4[2 * sub]);
            }
        }

        s_cur = (s_cur == NRING - 1) ? 0 : s_cur + 1;
        s_ld  = (s_ld  == NRING - 1) ? 0 : s_ld  + 1;
    }

    const int r = lane >> 2;
    const int cc = (lane & 3) * 2;
    #pragma unroll
    for (int f = 0; f < 2; ++f) {
        #pragma unroll
        for (int nf = 0; nf < 8; ++nf) {
            const float* c = acc[f][nf];
            const int col0 = colBase + warp_n * 64 + nf * 8 + cc;
            const int row0 = rowBase + warp_m * 32 + f * 16 + r;
            const float b0 = bias[col0], b1 = bias[col0 + 1];
            #pragma unroll
            for (int rr = 0; rr < 2; ++rr) {
                const int row = row0 + rr * 8;
                const float v0 = (c[rr * 2 + 0] + b0) * oscale;
                const float v1 = (c[rr * 2 + 1] + b1) * oscale;
                if (outMode == 2) {
                    float* p = &Yf32[(size_t)row * C_ + col0];
                    p[0] = v0; p[1] = v1;
                } else {
                    const int bb = row >> 11, i = row & (N_ - 1);
                    const int h = col0 >> 6, dd = col0 & 63;
                    const size_t idx = ((size_t)(bb * H_ + h) * N_ + i) * D_ + dd;
                    if (outMode == 0) {
                        uint32_t hi, lo;
                        split2h(v0, v1, hi, lo);
                        *reinterpret_cast<uint32_t*>(&Yhi[idx]) = hi;
                        *reinterpret_cast<uint32_t*>(&Ylo[idx]) = lo;
                    } else {
                        *reinterpret_cast<uint32_t*>(&Yhi[idx]) = pack_h2(v0, v1);
                    }
                }
            }
        }
    }
}

__global__ __launch_bounds__(256, 2)
void mha_qkv_ps_kernel(const float* __restrict__ bq, const float* __restrict__ bk,
                       const float* __restrict__ bv)
{
    extern __shared__ __align__(16) char sm[];
    const int z = blockIdx.z;
    const __half* As = g_X1 + (size_t)z * XSEG;
    const __half* Bs = g_W + (size_t)z * WSEG;
    if (z == 0) {
        gemm_h1_tile(As, Bs, bq, nullptr, g_Qhi, g_Qlo, QSCALE, 0,
                     blockIdx.y * BM, blockIdx.x * BN, sm);
    } else if (z == 1) {
        gemm_h1_tile(As, Bs, bk, nullptr, g_K1, nullptr, 1.0f, 1,
                     blockIdx.y * BM, blockIdx.x * BN, sm);
    } else {
        gemm_h1_tile(As, Bs, bv, nullptr, g_V1, nullptr, 1.0f, 1,
                     blockIdx.y * BM, blockIdx.x * BN, sm);
    }
}

__global__ __launch_bounds__(256, 2)
void mha_out_ps_kernel(const float* __restrict__ bo, float* __restrict__ out)
{
    extern __shared__ __align__(16) char sm[];
    gemm_h1_tile(g_AO1, g_W + 3 * WSEG, bo, out, nullptr, nullptr,
                 1.0f, 2, blockIdx.y * BM, blockIdx.x * BN, sm);
}

// ---------------------------------------------------------------------------
// K2: fp16 tensor-core flash attention. Q split (A), K/V single; P hi-only.
// 2-stage KV double buffer (R14-proven).
// ---------------------------------------------------------------------------
__device__ __forceinline__ void issue_kv(uint32_t dstbase, int tid,
                                         const __half* kk, const __half* vv)
{
    #pragma unroll
    for (int l = 0; l < 2; l++) {
        int cid = tid + l * 256;
        int row = cid >> 3, c8 = cid & 7;
        uint32_t off = (uint32_t)(row * APITCH + c8 * 16);
        const size_t g = (size_t)row * 64 + c8 * 8;
        cpa16(dstbase + off,         kk + g);
        cpa16(dstbase + KTILE + off, vv + g);
    }
}

__global__ __launch_bounds__(256, 2)
void mha_attn_tc_kernel()
{
    extern __shared__ __align__(16) char sm[];
    const uint32_t sb = smem_u32(sm);
    const int tid = threadIdx.x;
    const int lane = tid & 31;
    const int wid = tid >> 5;
    const int bh = blockIdx.y;
    const int qt = blockIdx.x;

    const size_t hbase = (size_t)bh * N_ * D_;
    {
        const __half* qh = g_Qhi + hbase + (size_t)qt * 128 * D_;
        const __half* ql = g_Qlo + hbase + (size_t)qt * 128 * D_;
        #pragma unroll
        for (int l = 0; l < 4; l++) {
            int cid = tid + l * 256;
            int row = cid >> 3, c8 = cid & 7;
            const size_t g = (size_t)row * 64 + c8 * 8;
            uint32_t off = (uint32_t)(row * APITCH + c8 * 16);
            *reinterpret_cast<uint4*>(sm + off) = *reinterpret_cast<const uint4*>(qh + g);
            *reinterpret_cast<uint4*>(sm + QTILE + off) = *reinterpret_cast<const uint4*>(ql + g);
        }
    }

    issue_kv(sb + 2 * QTILE, tid, g_K1 + hbase, g_V1 + hbase);
    cp_commit();

    float mA = -1e30f, mB = -1e30f, lA = 0.0f, lB = 0.0f;
    float oacc[8][4] = {};

    const uint32_t qrow = sb + (uint32_t)((wid * 16 + (lane & 15)) * APITCH + (lane >> 4) * 16);
    const uint32_t krow = (uint32_t)((((lane & 7) | ((lane & 16) >> 1)) * APITCH) + (lane & 8) * 2);
    const uint32_t vrow = (uint32_t)((lane & 15) * APITCH + (lane >> 4) * 16);

    constexpr int NKT = N_ / 64;   // 32
    for (int kt = 0; kt < NKT; ++kt) {
        cp_wait<0>();
        __syncthreads();
        if (kt + 1 < NKT) {
            issue_kv(sb + 2 * QTILE + (uint32_t)((kt + 1) & 1) * KV_STAGE, tid,
                     g_K1 + hbase + (size_t)(kt + 1) * 64 * D_,
                     g_V1 + hbase + (size_t)(kt + 1) * 64 * D_);
        }
        cp_commit();

        const uint32_t kb = sb + 2 * QTILE + (uint32_t)(kt & 1) * KV_STAGE;
        const uint32_t Ks = kb, Vs = kb + KTILE;

        // S (16 q-rows x 64 keys), log2 domain; Q 2-term
        float sacc[8][4] = {};
        #pragma unroll
        for (int ks = 0; ks < 4; ++ks) {
            uint32_t qh4[4], ql4[4];
            ldm_x4(qh4, qrow + ks * 32);
            ldm_x4(ql4, qrow + QTILE + ks * 32);
            #pragma unroll
            for (int t = 0; t < 4; ++t) {
                uint32_t k4[4];
                ldm_x4(k4, Ks + krow + t * 16 * APITCH + ks * 32);
                mma16816(sacc[t * 2 + 0], qh4, &k4[0]);
                mma16816(sacc[t * 2 + 1], qh4, &k4[2]);
                mma16816(sacc[t * 2 + 0], ql4, &k4[0]);
                mma16816(sacc[t * 2 + 1], ql4, &k4[2]);
            }
        }

        // Online softmax (base-2)
        float tA = -1e30f, tB = -1e30f;
        #pragma unroll
        for (int f = 0; f < 8; ++f) {
            tA = fmaxf(tA, fmaxf(sacc[f][0], sacc[f][1]));
            tB = fmaxf(tB, fmaxf(sacc[f][2], sacc[f][3]));
        }
        tA = fmaxf(tA, __shfl_xor_sync(0xffffffffu, tA, 1));
        tA = fmaxf(tA, __shfl_xor_sync(0xffffffffu, tA, 2));
        tB = fmaxf(tB, __shfl_xor_sync(0xffffffffu, tB, 1));
        tB = fmaxf(tB, __shfl_xor_sync(0xffffffffu, tB, 2));
        const float nmA = fmaxf(mA, tA), nmB = fmaxf(mB, tB);
        const float cA = ex2f(mA - nmA), cB = ex2f(mB - nmB);
        mA = nmA; mB = nmB;

        float psA = 0.0f, psB = 0.0f;
        #pragma unroll
        for (int f = 0; f < 8; ++f) {
            float p0 = ex2f(sacc[f][0] - mA);
            float p1 = ex2f(sacc[f][1] - mA);
            float p2 = ex2f(sacc[f][2] - mB);
            float p3 = ex2f(sacc[f][3] - mB);
            sacc[f][0] = p0; sacc[f][1] = p1; sacc[f][2] = p2; sacc[f][3] = p3;
            psA += p0 + p1; psB += p2 + p3;
        }
        lA = lA * cA + psA;
        lB = lB * cB + psB;
        #pragma unroll
        for (int nf = 0; nf < 8; ++nf) {
            oacc[nf][0] *= cA; oacc[nf][1] *= cA;
            oacc[nf][2] *= cB; oacc[nf][3] *= cB;
        }

        // O += P @ V  (P hi-only fp16; V single)
        #pragma unroll
        for (int ks = 0; ks < 4; ++ks) {
            uint32_t phi[4];
            phi[0] = pack_h2(sacc[2 * ks][0],     sacc[2 * ks][1]);
            phi[1] = pack_h2(sacc[2 * ks][2],     sacc[2 * ks][3]);
            phi[2] = pack_h2(sacc[2 * ks + 1][0], sacc[2 * ks + 1][1]);
            phi[3] = pack_h2(sacc[2 * ks + 1][2], sacc[2 * ks + 1][3]);
            const uint32_t vb = vrow + (uint32_t)(16 * ks * APITCH);
            #pragma unroll
            for (int dg = 0; dg < 4; ++dg) {
                uint32_t v4[4];
                ldm_x4_t(v4, Vs + vb + dg * 32);
                mma16816(oacc[2 * dg],     phi, &v4[0]);
                mma16816(oacc[2 * dg + 1], phi, &v4[2]);
            }
        }
    }

    lA += __shfl_xor_sync(0xffffffffu, lA, 1);
    lA += __shfl_xor_sync(0xffffffffu, lA, 2);
    lB += __shfl_xor_sync(0xffffffffu, lB, 1);
    lB += __shfl_xor_sync(0xffffffffu, lB, 2);
    const float iA = 1.0f / lA, iB = 1.0f / lB;

    const int b = bh >> 4;
    const int h = bh & 15;
    const int rowA = qt * 128 + wid * 16 + (lane >> 2);
    #pragma unroll
    for (int nf = 0; nf < 8; ++nf) {
        const int d0 = nf * 8 + (lane & 3) * 2;
        const size_t iA0 = (size_t)(b * N_ + rowA) * C_ + h * 64 + d0;
        const size_t iB0 = (size_t)(b * N_ + rowA + 8) * C_ + h * 64 + d0;
        *reinterpret_cast<uint32_t*>(&g_AO1[iA0]) = pack_h2(oacc[nf][0] * iA, oacc[nf][1] * iA);
        *reinterpret_cast<uint32_t*>(&g_AO1[iB0]) = pack_h2(oacc[nf][2] * iB, oacc[nf][3] * iB);
    }
}

// ---------------------------------------------------------------------------
extern "C" void kernel_launch(void* const* d_in, const int* in_sizes, int n_in,
                              void* d_out, int out_size)
{
    (void)in_sizes; (void)n_in; (void)out_size;
    const float* q  = (const float*)d_in[0];
    const float* k  = (const float*)d_in[1];
    const float* v  = (const float*)d_in[2];
    const float* wq = (const float*)d_in[3];
    const float* bq = (const float*)d_in[4];
    const float* wk = (const float*)d_in[5];
    const float* bk = (const float*)d_in[6];
    const float* wv = (const float*)d_in[7];
    const float* bv = (const float*)d_in[8];
    const float* wo = (const float*)d_in[9];
    const float* bo = (const float*)d_in[10];
    float* out = (float*)d_out;

    cudaFuncSetAttribute(mha_qkv_ps_kernel,
                         cudaFuncAttributeMaxDynamicSharedMemorySize, GEMM_SMEM);
    cudaFuncSetAttribute(mha_out_ps_kernel,
                         cudaFuncAttributeMaxDynamicSharedMemorySize, GEMM_SMEM);
    cudaFuncSetAttribute(mha_attn_tc_kernel,
                         cudaFuncAttributeMaxDynamicSharedMemorySize, ATTN_SMEM);

    dim3 gsplit(XSEG / 4 / 256, 7);
    split_convert_kernel<<<gsplit, 256>>>(q, k, v, wq, wk, wv, wo);

    dim3 gproj(C_ / BN, (B_ * N_) / BM, 3);   // 8 x 32 x 3
    mha_qkv_ps_kernel<<<gproj, 256, GEMM_SMEM>>>(bq, bk, bv);

    dim3 gattn(N_ / 128, B_ * H_);            // 16 x 32
    mha_attn_tc_kernel<<<gattn, 256, ATTN_SMEM>>>();

    dim3 gout(C_ / BN, (B_ * N_) / BM);       // 8 x 32
    mha_out_ps_kernel<<<gout, 256, GEMM_SMEM>>>(bo, out);
}